// round 13
// baseline (speedup 1.0000x reference)
#include <cuda_runtime.h>
#include <cstdint>

// x:     (128, 9, 84, 420) fp32
// shift: (128, 2) int32, values in [0, 8]
// out[n,c,i,j] = x[n,c, yy, xx]
//   yy = max(ky + i - 4, 0) % 84      (upper clamp never binds; range [-4,87])
//   xx = clamp(kx + j - 4, 0, 419)

#define N_   128
#define C_   9
#define H_   84
#define W_   420
#define W4_  (W_ / 4)                 // 105 float4 per row
#define ROWS (N_ * C_ * H_)           // 96768

#define JS    5                       // j-slices per thread
#define J_OFF (W4_ / JS)              // 21 float4 stride within the row
#define TT    (ROWS * J_OFF)          // 2,032,128 threads

__global__ void __launch_bounds__(256)
random_shifts_kernel(const float* __restrict__ x,
                     const int*   __restrict__ shift,
                     float*       __restrict__ out)
{
    int t = blockIdx.x * blockDim.x + threadIdx.x;
    if (t >= TT) return;

    int j4  = t % J_OFF;        // base j4 in [0, 21)
    int row = t / J_OFF;        // (n*C + c)*H + i
    int i   = row % H_;
    int nc  = row / H_;
    int n   = nc / C_;

    int kx = __ldg(&shift[2 * n + 0]);
    int ky = __ldg(&shift[2 * n + 1]);

    // vertical index: clamp at 0, then wrap (tile) at 84 — shared by all 5 outputs
    int yy = ky + i - 4;
    yy = max(yy, 0);
    if (yy >= H_) yy -= H_;

    const float*  src  = x + ((size_t)nc * H_ + yy) * W_;
    const float4* src4 = reinterpret_cast<const float4*>(src);
    int r = kx & 3;             // misalignment — uniform per image

    int  b[JS];
    bool f[JS];
#pragma unroll
    for (int s = 0; s < JS; s++) {
        b[s] = kx + (j4 + s * J_OFF) * 4 - 4;
        f[s] = (b[s] >= 0) && (b[s] <= W_ - 8);
    }

    // Front-batched loads: up to 10 independent LDG.128 in flight
    float4 A[JS], B[JS];
#pragma unroll
    for (int s = 0; s < JS; s++) {
        if (f[s]) {
            int q = b[s] >> 2;
            A[s] = __ldg(src4 + q);
            B[s] = __ldg(src4 + q + 1);
        }
    }

    float4 v[JS];
#pragma unroll
    for (int s = 0; s < JS; s++) {
        if (f[s]) {
            float4 a = A[s], bb = B[s];
            v[s].x = (r == 0) ? a.x : (r == 1) ? a.y : (r == 2) ? a.z : a.w;
            v[s].y = (r == 0) ? a.y : (r == 1) ? a.z : (r == 2) ? a.w : bb.x;
            v[s].z = (r == 0) ? a.z : (r == 1) ? a.w : (r == 2) ? bb.x : bb.y;
            v[s].w = (r == 0) ? a.w : (r == 1) ? bb.x : (r == 2) ? bb.y : bb.z;
        } else {
            int bs = b[s];
            int e0 = min(max(bs + 0, 0), W_ - 1);
            int e1 = min(max(bs + 1, 0), W_ - 1);
            int e2 = min(max(bs + 2, 0), W_ - 1);
            int e3 = min(max(bs + 3, 0), W_ - 1);
            v[s].x = __ldg(src + e0);
            v[s].y = __ldg(src + e1);
            v[s].z = __ldg(src + e2);
            v[s].w = __ldg(src + e3);
        }
    }

    // Coalesced streaming stores: five contiguous 336B-stride runs per warp
    float4* out4 = reinterpret_cast<float4*>(out) + (size_t)row * W4_ + j4;
#pragma unroll
    for (int s = 0; s < JS; s++) {
        __stcs(out4 + s * J_OFF, v[s]);
    }
}

extern "C" void kernel_launch(void* const* d_in, const int* in_sizes, int n_in,
                              void* d_out, int out_size)
{
    const float* x     = (const float*)d_in[0];
    const int*   shift = (const int*)d_in[1];
    float*       out   = (float*)d_out;

    const int threads = 256;
    const int blocks  = (TT + threads - 1) / threads;
    random_shifts_kernel<<<blocks, threads>>>(x, shift, out);
}